// round 1
// baseline (speedup 1.0000x reference)
#include <cuda_runtime.h>

// Problem constants
#define B_   2048
#define MND  128
#define D_   512
#define H_   512
#define KB   2048   // big-GEMM K = 4*512

// Scratch (device globals: no allocations allowed)
__device__ float g_X[(size_t)B_ * KB];      // [2048,2048] = [img_mean|txt_mean|it|ii]
__device__ float g_Wbig[(size_t)H_ * KB];   // [512,2048]  = [W_l_img|W_l_txt|Wc]
__device__ float g_Wrc[H_ * H_];            // W_r_img + W_r_txt
__device__ float g_bc[H_];                  // combined bias

// ---------------------------------------------------------------------------
// prep: Wbig[:,0:512]=W_l_img, Wbig[:,512:1024]=W_l_txt, Wrc = Wr_img+Wr_txt
// ---------------------------------------------------------------------------
__global__ void prep_kernel(const float* __restrict__ Wl_img,
                            const float* __restrict__ Wl_txt,
                            const float* __restrict__ Wr_img,
                            const float* __restrict__ Wr_txt) {
    int idx = blockIdx.x * blockDim.x + threadIdx.x;      // 0 .. 524287
    if (idx < H_ * 1024) {
        int h = idx >> 10, c = idx & 1023;
        g_Wbig[h * KB + c] = (c < 512) ? Wl_img[h * 512 + c]
                                       : Wl_txt[h * 512 + (c - 512)];
    }
    if (idx < H_ * H_) g_Wrc[idx] = Wr_img[idx] + Wr_txt[idx];
}

// ---------------------------------------------------------------------------
// bc[h] = b_l_img[h] + b_l_txt[h] + sum_k Wrc[h,k] * b_user[k]
// ---------------------------------------------------------------------------
__global__ void bc_kernel(const float* __restrict__ b_user,
                          const float* __restrict__ bl_img,
                          const float* __restrict__ bl_txt) {
    int h = blockIdx.x;
    int t = threadIdx.x;  // 128 threads
    float s = 0.0f;
    for (int k = t; k < H_; k += 128) s += g_Wrc[h * H_ + k] * b_user[k];
    __shared__ float red[4];
    #pragma unroll
    for (int o = 16; o; o >>= 1) s += __shfl_down_sync(0xffffffffu, s, o);
    if ((t & 31) == 0) red[t >> 5] = s;
    __syncthreads();
    if (t == 0)
        g_bc[h] = red[0] + red[1] + red[2] + red[3] + bl_img[h] + bl_txt[h];
}

// ---------------------------------------------------------------------------
// means: for each b, X[b] = [mean_m img[b,m,:] | mean_m txt[b,m,:] | it[b] | ii[b]]
// Fully coalesced float4 streaming. One block per b, 256 threads.
// ---------------------------------------------------------------------------
__global__ void means_kernel(const float* __restrict__ img,
                             const float* __restrict__ txt,
                             const float* __restrict__ it,
                             const float* __restrict__ ii) {
    int b = blockIdx.x;
    int t = threadIdx.x;             // 0..255
    int h4 = t & 127;                // float4 index within 512 floats
    const float* src = (t < 128) ? img : txt;
    const float4* base = (const float4*)(src + (size_t)b * MND * H_) + h4;

    float4 acc = make_float4(0.f, 0.f, 0.f, 0.f);
    #pragma unroll 8
    for (int m = 0; m < MND; m++) {
        float4 v = base[(size_t)m * (H_ / 4)];
        acc.x += v.x; acc.y += v.y; acc.z += v.z; acc.w += v.w;
    }
    const float inv = 1.0f / (float)MND;
    acc.x *= inv; acc.y *= inv; acc.z *= inv; acc.w *= inv;

    float4* xrow = (float4*)(g_X + (size_t)b * KB);
    // img_mean -> cols [0,512), txt_mean -> [512,1024)
    xrow[(t < 128 ? 0 : 128) + h4] = acc;

    // it -> cols [1024,1536), ii -> [1536,2048)
    const float4* cs = (const float4*)(((t < 128) ? it : ii) + (size_t)b * D_);
    xrow[(t < 128 ? 256 : 384) + h4] = cs[h4];
}

// ---------------------------------------------------------------------------
// Wc = Wrc @ W_user   (M=512 rows h, N=1024 cols j, K=512), NN layout.
// Result into g_Wbig[:, 1024:2048].
// 64x64x16 tiles, 256 threads, 4x4 per thread.
// ---------------------------------------------------------------------------
__global__ void gemm_nn_wc(const float* __restrict__ Wuser) {
    __shared__ float As[16][68];
    __shared__ float Bs[16][68];
    const int bn = blockIdx.x;            // 0..15 (j)
    const int bm = blockIdx.y;            // 0..7  (h)
    const int tid = threadIdx.x;
    const int tn = tid & 15, tm = tid >> 4;
    const int ar = tid >> 2, akv = tid & 3;
    const int brow = tid >> 4, bc4 = tid & 15;

    const float* Ap = g_Wrc + (size_t)(bm * 64 + ar) * 512 + akv * 4;
    const float* Bp = Wuser + (size_t)brow * 1024 + bn * 64 + bc4 * 4;

    float acc[4][4] = {};
    for (int k0 = 0; k0 < 512; k0 += 16) {
        float4 av = *(const float4*)(Ap + k0);
        float4 bv = *(const float4*)(Bp + (size_t)k0 * 1024);
        __syncthreads();
        As[akv * 4 + 0][ar] = av.x; As[akv * 4 + 1][ar] = av.y;
        As[akv * 4 + 2][ar] = av.z; As[akv * 4 + 3][ar] = av.w;
        *(float4*)&Bs[brow][bc4 * 4] = bv;
        __syncthreads();
        #pragma unroll
        for (int k = 0; k < 16; k++) {
            float4 a = *(const float4*)&As[k][tm * 4];
            float4 b = *(const float4*)&Bs[k][tn * 4];
            acc[0][0] += a.x * b.x; acc[0][1] += a.x * b.y; acc[0][2] += a.x * b.z; acc[0][3] += a.x * b.w;
            acc[1][0] += a.y * b.x; acc[1][1] += a.y * b.y; acc[1][2] += a.y * b.z; acc[1][3] += a.y * b.w;
            acc[2][0] += a.z * b.x; acc[2][1] += a.z * b.y; acc[2][2] += a.z * b.z; acc[2][3] += a.z * b.w;
            acc[3][0] += a.w * b.x; acc[3][1] += a.w * b.y; acc[3][2] += a.w * b.z; acc[3][3] += a.w * b.w;
        }
    }
    int row = bm * 64 + tm * 4;
    int col = bn * 64 + tn * 4;
    #pragma unroll
    for (int i = 0; i < 4; i++) {
        float4 v = make_float4(acc[i][0], acc[i][1], acc[i][2], acc[i][3]);
        *(float4*)&g_Wbig[(size_t)(row + i) * KB + 1024 + col] = v;
    }
}

// ---------------------------------------------------------------------------
// out = relu( X @ Wbig^T + bc )   (M=2048, N=512, K=2048), NT layout.
// 64x64x16 tiles, 256 threads, 4x4 per thread, fused bias+ReLU.
// ---------------------------------------------------------------------------
__global__ void gemm_out(float* __restrict__ C) {
    __shared__ float As[16][68];
    __shared__ float Bs[16][68];
    const int bn = blockIdx.x;            // 0..7  (h)
    const int bm = blockIdx.y;            // 0..31 (b)
    const int tid = threadIdx.x;
    const int tn = tid & 15, tm = tid >> 4;
    const int ar = tid >> 2, akv = tid & 3;

    const float* Ap = g_X    + (size_t)(bm * 64 + ar) * KB + akv * 4;
    const float* Bp = g_Wbig + (size_t)(bn * 64 + ar) * KB + akv * 4;

    float acc[4][4] = {};
    for (int k0 = 0; k0 < KB; k0 += 16) {
        float4 av = *(const float4*)(Ap + k0);
        float4 bv = *(const float4*)(Bp + k0);
        __syncthreads();
        As[akv * 4 + 0][ar] = av.x; As[akv * 4 + 1][ar] = av.y;
        As[akv * 4 + 2][ar] = av.z; As[akv * 4 + 3][ar] = av.w;
        Bs[akv * 4 + 0][ar] = bv.x; Bs[akv * 4 + 1][ar] = bv.y;
        Bs[akv * 4 + 2][ar] = bv.z; Bs[akv * 4 + 3][ar] = bv.w;
        __syncthreads();
        #pragma unroll
        for (int k = 0; k < 16; k++) {
            float4 a = *(const float4*)&As[k][tm * 4];
            float4 b = *(const float4*)&Bs[k][tn * 4];
            acc[0][0] += a.x * b.x; acc[0][1] += a.x * b.y; acc[0][2] += a.x * b.z; acc[0][3] += a.x * b.w;
            acc[1][0] += a.y * b.x; acc[1][1] += a.y * b.y; acc[1][2] += a.y * b.z; acc[1][3] += a.y * b.w;
            acc[2][0] += a.z * b.x; acc[2][1] += a.z * b.y; acc[2][2] += a.z * b.z; acc[2][3] += a.z * b.w;
            acc[3][0] += a.w * b.x; acc[3][1] += a.w * b.y; acc[3][2] += a.w * b.z; acc[3][3] += a.w * b.w;
        }
    }
    int row = bm * 64 + tm * 4;
    int col = bn * 64 + tn * 4;
    float4 bias = *(const float4*)&g_bc[col];
    #pragma unroll
    for (int i = 0; i < 4; i++) {
        float4 v;
        v.x = fmaxf(acc[i][0] + bias.x, 0.f);
        v.y = fmaxf(acc[i][1] + bias.y, 0.f);
        v.z = fmaxf(acc[i][2] + bias.z, 0.f);
        v.w = fmaxf(acc[i][3] + bias.w, 0.f);
        *(float4*)&C[(size_t)(row + i) * H_ + col] = v;
    }
}

// ---------------------------------------------------------------------------
extern "C" void kernel_launch(void* const* d_in, const int* in_sizes, int n_in,
                              void* d_out, int out_size) {
    const float* it      = (const float*)d_in[0];   // input_text  [2048,1,512]
    const float* ii      = (const float*)d_in[1];   // input_img   [2048,1,512]
    const float* txt     = (const float*)d_in[2];   // base_text_features [2048,128,512]
    const float* img     = (const float*)d_in[3];   // base_img_features  [2048,128,512]
    const float* W_user  = (const float*)d_in[4];   // [512,1024]
    const float* b_user  = (const float*)d_in[5];   // [512]
    const float* Wl_img  = (const float*)d_in[6];   // [512,512]
    const float* bl_img  = (const float*)d_in[7];   // [512]
    const float* Wr_img  = (const float*)d_in[8];   // [512,512]
    const float* Wl_txt  = (const float*)d_in[9];   // [512,512]
    const float* bl_txt  = (const float*)d_in[10];  // [512]
    const float* Wr_txt  = (const float*)d_in[11];  // [512,512]
    float* out = (float*)d_out;                     // [2048,512]

    // 1) assemble Wbig cols [0,1024) and Wrc
    prep_kernel<<<2048, 256>>>(Wl_img, Wl_txt, Wr_img, Wr_txt);

    // 2) Wc = Wrc @ W_user -> Wbig cols [1024,2048)
    {
        dim3 grid(1024 / 64, 512 / 64);
        gemm_nn_wc<<<grid, 256>>>(W_user);
    }

    // 3) combined bias
    bc_kernel<<<512, 128>>>(b_user, bl_img, bl_txt);

    // 4) means + concat -> X   (reads the 1.07 GB; the HBM-bound stage)
    means_kernel<<<B_, 256>>>(img, txt, it, ii);

    // 5) out = relu(X @ Wbig^T + bc)
    {
        dim3 grid(512 / 64, 2048 / 64);
        gemm_out<<<grid, 256>>>(out);
    }
}

// round 2
// speedup vs baseline: 1.0974x; 1.0974x over previous
#include <cuda_runtime.h>
#include <cstdint>

// Problem constants
#define B_   2048
#define MND  128
#define D_   512
#define H_   512
#define KB   2048   // big-GEMM K = 4*512

// Scratch (device globals: no allocations allowed)
__device__ float g_X[(size_t)B_ * KB];      // [2048,2048] = [img_mean|txt_mean|it|ii] (tf32-rounded)
__device__ float g_Wbig[(size_t)H_ * KB];   // [512,2048]  = [W_l_img|W_l_txt|Wc]     (tf32-rounded)
__device__ float g_Wrc[H_ * H_];            // W_r_img + W_r_txt (fp32)
__device__ float g_bc[H_];                  // combined bias (fp32)

// Round fp32 -> tf32 (rna), returned as fp32 with low mantissa bits zeroed.
__device__ __forceinline__ float tf32r(float x) {
    uint32_t u;
    asm("cvt.rna.tf32.f32 %0, %1;" : "=r"(u) : "f"(x));
    return __uint_as_float(u);
}

// ---------------------------------------------------------------------------
// prep: Wbig[:,0:512]=W_l_img, Wbig[:,512:1024]=W_l_txt (tf32), Wrc = Wr_img+Wr_txt
// ---------------------------------------------------------------------------
__global__ void prep_kernel(const float* __restrict__ Wl_img,
                            const float* __restrict__ Wl_txt,
                            const float* __restrict__ Wr_img,
                            const float* __restrict__ Wr_txt) {
    int idx = blockIdx.x * blockDim.x + threadIdx.x;      // 0 .. 524287
    if (idx < H_ * 1024) {
        int h = idx >> 10, c = idx & 1023;
        float v = (c < 512) ? Wl_img[h * 512 + c] : Wl_txt[h * 512 + (c - 512)];
        g_Wbig[h * KB + c] = tf32r(v);
    }
    if (idx < H_ * H_) g_Wrc[idx] = Wr_img[idx] + Wr_txt[idx];
}

// ---------------------------------------------------------------------------
// bc[h] = b_l_img[h] + b_l_txt[h] + sum_k Wrc[h,k] * b_user[k]   (exact fp32)
// ---------------------------------------------------------------------------
__global__ void bc_kernel(const float* __restrict__ b_user,
                          const float* __restrict__ bl_img,
                          const float* __restrict__ bl_txt) {
    int h = blockIdx.x;
    int t = threadIdx.x;  // 128 threads
    float s = 0.0f;
    for (int k = t; k < H_; k += 128) s += g_Wrc[h * H_ + k] * b_user[k];
    __shared__ float red[4];
    #pragma unroll
    for (int o = 16; o; o >>= 1) s += __shfl_down_sync(0xffffffffu, s, o);
    if ((t & 31) == 0) red[t >> 5] = s;
    __syncthreads();
    if (t == 0)
        g_bc[h] = red[0] + red[1] + red[2] + red[3] + bl_img[h] + bl_txt[h];
}

// ---------------------------------------------------------------------------
// means: X[b] = [mean_m img | mean_m txt | it | ii]  (tf32-rounded on write)
// HBM-bound stage: reads 1.07 GB fully coalesced as float4.
// ---------------------------------------------------------------------------
__global__ void means_kernel(const float* __restrict__ img,
                             const float* __restrict__ txt,
                             const float* __restrict__ it,
                             const float* __restrict__ ii) {
    int b = blockIdx.x;
    int t = threadIdx.x;             // 0..255
    int h4 = t & 127;                // float4 index within 512 floats
    const float* src = (t < 128) ? img : txt;
    const float4* base = (const float4*)(src + (size_t)b * MND * H_) + h4;

    float4 acc = make_float4(0.f, 0.f, 0.f, 0.f);
    #pragma unroll 16
    for (int m = 0; m < MND; m++) {
        float4 v = base[(size_t)m * (H_ / 4)];
        acc.x += v.x; acc.y += v.y; acc.z += v.z; acc.w += v.w;
    }
    const float inv = 1.0f / (float)MND;
    float4 o;
    o.x = tf32r(acc.x * inv); o.y = tf32r(acc.y * inv);
    o.z = tf32r(acc.z * inv); o.w = tf32r(acc.w * inv);

    float4* xrow = (float4*)(g_X + (size_t)b * KB);
    xrow[(t < 128 ? 0 : 128) + h4] = o;

    // it -> cols [1024,1536), ii -> [1536,2048)
    const float4* cs = (const float4*)(((t < 128) ? it : ii) + (size_t)b * D_);
    float4 c = cs[h4];
    c.x = tf32r(c.x); c.y = tf32r(c.y); c.z = tf32r(c.z); c.w = tf32r(c.w);
    xrow[(t < 128 ? 256 : 384) + h4] = c;
}

// ---------------------------------------------------------------------------
// Wc = Wrc @ W_user   (M=512, N=1024, K=512), fp32 SIMT, NN layout.
// Result (tf32-rounded) into g_Wbig[:, 1024:2048].
// ---------------------------------------------------------------------------
__global__ void gemm_nn_wc(const float* __restrict__ Wuser) {
    __shared__ float As[16][68];
    __shared__ float Bs[16][68];
    const int bn = blockIdx.x;            // 0..15 (j)
    const int bm = blockIdx.y;            // 0..7  (h)
    const int tid = threadIdx.x;
    const int tn = tid & 15, tm = tid >> 4;
    const int ar = tid >> 2, akv = tid & 3;
    const int brow = tid >> 4, bc4 = tid & 15;

    const float* Ap = g_Wrc + (size_t)(bm * 64 + ar) * 512 + akv * 4;
    const float* Bp = Wuser + (size_t)brow * 1024 + bn * 64 + bc4 * 4;

    float acc[4][4] = {};
    for (int k0 = 0; k0 < 512; k0 += 16) {
        float4 av = *(const float4*)(Ap + k0);
        float4 bv = *(const float4*)(Bp + (size_t)k0 * 1024);
        __syncthreads();
        As[akv * 4 + 0][ar] = av.x; As[akv * 4 + 1][ar] = av.y;
        As[akv * 4 + 2][ar] = av.z; As[akv * 4 + 3][ar] = av.w;
        *(float4*)&Bs[brow][bc4 * 4] = bv;
        __syncthreads();
        #pragma unroll
        for (int k = 0; k < 16; k++) {
            float4 a = *(const float4*)&As[k][tm * 4];
            float4 b = *(const float4*)&Bs[k][tn * 4];
            acc[0][0] += a.x * b.x; acc[0][1] += a.x * b.y; acc[0][2] += a.x * b.z; acc[0][3] += a.x * b.w;
            acc[1][0] += a.y * b.x; acc[1][1] += a.y * b.y; acc[1][2] += a.y * b.z; acc[1][3] += a.y * b.w;
            acc[2][0] += a.z * b.x; acc[2][1] += a.z * b.y; acc[2][2] += a.z * b.z; acc[2][3] += a.z * b.w;
            acc[3][0] += a.w * b.x; acc[3][1] += a.w * b.y; acc[3][2] += a.w * b.z; acc[3][3] += a.w * b.w;
        }
    }
    int row = bm * 64 + tm * 4;
    int col = bn * 64 + tn * 4;
    #pragma unroll
    for (int i = 0; i < 4; i++) {
        float4 v = make_float4(tf32r(acc[i][0]), tf32r(acc[i][1]),
                               tf32r(acc[i][2]), tf32r(acc[i][3]));
        *(float4*)&g_Wbig[(size_t)(row + i) * KB + 1024 + col] = v;
    }
}

// ---------------------------------------------------------------------------
// out = relu( X @ Wbig^T + bc )  via mma.sync.m16n8k8.tf32
// M=2048, N=512, K=2048. BM=128, BN=64, BK=16, 256 threads (8 warps, 4m x 2n),
// warp tile 32x32 = 2x4 mma tiles. Smem double-buffered, row-stride 20 floats
// -> conflict-free fragment LDS ((20g+tg) mod 32 all distinct).
// ---------------------------------------------------------------------------
#define BM 128
#define BN 64
#define BKT 16
#define STR 20

__global__ __launch_bounds__(256) void gemm_out_tf32(float* __restrict__ C) {
    __shared__ float As[2][BM * STR];   // [m][k]
    __shared__ float Bs[2][BN * STR];   // [n][k]
    const int tid = threadIdx.x;
    const int bn0 = blockIdx.x * BN;
    const int bm0 = blockIdx.y * BM;

    const int w    = tid >> 5;
    const int lane = tid & 31;
    const int wm = (w & 3) * 32;       // warp m offset in tile
    const int wn = (w >> 2) * 32;      // warp n offset in tile
    const int g  = lane >> 2;          // 0..7
    const int tg = lane & 3;           // 0..3

    const int lr = tid >> 2;           // 0..63 (tile row for loads)
    const int lc = (tid & 3) * 4;      // k offset 0,4,8,12

    const float* Xp = g_X    + (size_t)(bm0 + lr) * KB + lc;
    const float* Wp = g_Wbig + (size_t)(bn0 + lr) * KB + lc;

    float acc[2][4][4];
    #pragma unroll
    for (int i = 0; i < 2; i++)
        #pragma unroll
        for (int j = 0; j < 4; j++)
            #pragma unroll
            for (int q = 0; q < 4; q++) acc[i][j][q] = 0.f;

    // preload tile 0
    {
        float4 xa = *(const float4*)(Xp);
        float4 xb = *(const float4*)(Xp + (size_t)64 * KB);
        float4 wv = *(const float4*)(Wp);
        *(float4*)&As[0][lr * STR + lc]        = xa;
        *(float4*)&As[0][(lr + 64) * STR + lc] = xb;
        *(float4*)&Bs[0][lr * STR + lc]        = wv;
    }
    __syncthreads();

    int p = 0;
    const int NKT = KB / BKT;   // 128
    for (int kt = 0; kt < NKT; kt++) {
        float4 nxa, nxb, nwv;
        const bool more = (kt + 1 < NKT);
        if (more) {
            const float* Xn = Xp + (kt + 1) * BKT;
            const float* Wn = Wp + (kt + 1) * BKT;
            nxa = *(const float4*)(Xn);
            nxb = *(const float4*)(Xn + (size_t)64 * KB);
            nwv = *(const float4*)(Wn);
        }

        #pragma unroll
        for (int ks = 0; ks < 2; ks++) {
            const int k = ks * 8;
            uint32_t af[2][4], bf[4][2];
            #pragma unroll
            for (int mi = 0; mi < 2; mi++) {
                const int m = wm + mi * 16;
                af[mi][0] = __float_as_uint(As[p][(m + g)     * STR + k + tg]);
                af[mi][1] = __float_as_uint(As[p][(m + g + 8) * STR + k + tg]);
                af[mi][2] = __float_as_uint(As[p][(m + g)     * STR + k + tg + 4]);
                af[mi][3] = __float_as_uint(As[p][(m + g + 8) * STR + k + tg + 4]);
            }
            #pragma unroll
            for (int ni = 0; ni < 4; ni++) {
                const int n = wn + ni * 8;
                bf[ni][0] = __float_as_uint(Bs[p][(n + g) * STR + k + tg]);
                bf[ni][1] = __float_as_uint(Bs[p][(n + g) * STR + k + tg + 4]);
            }
            #pragma unroll
            for (int mi = 0; mi < 2; mi++)
                #pragma unroll
                for (int ni = 0; ni < 4; ni++)
                    asm volatile(
                        "mma.sync.aligned.m16n8k8.row.col.f32.tf32.tf32.f32 "
                        "{%0,%1,%2,%3}, {%4,%5,%6,%7}, {%8,%9}, {%0,%1,%2,%3};\n"
                        : "+f"(acc[mi][ni][0]), "+f"(acc[mi][ni][1]),
                          "+f"(acc[mi][ni][2]), "+f"(acc[mi][ni][3])
                        : "r"(af[mi][0]), "r"(af[mi][1]), "r"(af[mi][2]), "r"(af[mi][3]),
                          "r"(bf[ni][0]), "r"(bf[ni][1]));
        }

        if (more) {
            const int q = p ^ 1;
            *(float4*)&As[q][lr * STR + lc]        = nxa;
            *(float4*)&As[q][(lr + 64) * STR + lc] = nxb;
            *(float4*)&Bs[q][lr * STR + lc]        = nwv;
        }
        __syncthreads();
        p ^= 1;
    }

    // epilogue: bias + ReLU
    #pragma unroll
    for (int mi = 0; mi < 2; mi++) {
        const int row0 = bm0 + wm + mi * 16 + g;
        #pragma unroll
        for (int ni = 0; ni < 4; ni++) {
            const int col = bn0 + wn + ni * 8 + tg * 2;
            const float b0v = g_bc[col], b1v = g_bc[col + 1];
            float2 v0, v1;
            v0.x = fmaxf(acc[mi][ni][0] + b0v, 0.f);
            v0.y = fmaxf(acc[mi][ni][1] + b1v, 0.f);
            v1.x = fmaxf(acc[mi][ni][2] + b0v, 0.f);
            v1.y = fmaxf(acc[mi][ni][3] + b1v, 0.f);
            *(float2*)&C[(size_t)row0 * H_ + col]       = v0;
            *(float2*)&C[(size_t)(row0 + 8) * H_ + col] = v1;
        }
    }
}

// ---------------------------------------------------------------------------
extern "C" void kernel_launch(void* const* d_in, const int* in_sizes, int n_in,
                              void* d_out, int out_size) {
    const float* it      = (const float*)d_in[0];   // input_text  [2048,1,512]
    const float* ii      = (const float*)d_in[1];   // input_img   [2048,1,512]
    const float* txt     = (const float*)d_in[2];   // base_text_features [2048,128,512]
    const float* img     = (const float*)d_in[3];   // base_img_features  [2048,128,512]
    const float* W_user  = (const float*)d_in[4];   // [512,1024]
    const float* b_user  = (const float*)d_in[5];   // [512]
    const float* Wl_img  = (const float*)d_in[6];   // [512,512]
    const float* bl_img  = (const float*)d_in[7];   // [512]
    const float* Wr_img  = (const float*)d_in[8];   // [512,512]
    const float* Wl_txt  = (const float*)d_in[9];   // [512,512]
    const float* bl_txt  = (const float*)d_in[10];  // [512]
    const float* Wr_txt  = (const float*)d_in[11];  // [512,512]
    float* out = (float*)d_out;                     // [2048,512]

    // 1) assemble Wbig cols [0,1024) and Wrc
    prep_kernel<<<2048, 256>>>(Wl_img, Wl_txt, Wr_img, Wr_txt);

    // 2) Wc = Wrc @ W_user -> Wbig cols [1024,2048)
    {
        dim3 grid(1024 / 64, 512 / 64);
        gemm_nn_wc<<<grid, 256>>>(W_user);
    }

    // 3) combined bias
    bc_kernel<<<512, 128>>>(b_user, bl_img, bl_txt);

    // 4) means + concat -> X   (the HBM-bound stage)
    means_kernel<<<B_, 256>>>(img, txt, it, ii);

    // 5) out = relu(X @ Wbig^T + bc)  -- tensor cores (tf32)
    {
        dim3 grid(H_ / BN, B_ / BM);
        gemm_out_tf32<<<grid, 256>>>(out);
    }
}